// round 3
// baseline (speedup 1.0000x reference)
#include <cuda_runtime.h>
#include <cuda_bf16.h>
#include <cstdint>
#include <cstddef>

#define NN   4096
#define FIN  512
#define DH   64
#define NH   8
#define NC   16
#define KH   2
#define MAXNBR 512

typedef unsigned long long ull;

// ---------------- scratch ----------------------------------------------------
__device__ __nv_bfloat162 g_Whb[(size_t)NH * NN * (DH / 2)]; // [H,N,D] bf16 (4 MB)
__device__ float g_f1[NH * NN];
__device__ float g_f2[NH * NN];
__device__ float g_Who[NN * NC];
__device__ float g_g1[NN];
__device__ float g_g2[NN];
__device__ int   g_nbr[(size_t)KH * NN * MAXNBR];
__device__ int   g_cnt[KH * NN];

// ---------------- f32x2 helpers ----------------------------------------------
__device__ __forceinline__ void fma2(ull& d, ull a, ull b) {
    asm("fma.rn.f32x2 %0, %1, %2, %0;" : "+l"(d) : "l"(a), "l"(b));
}
__device__ __forceinline__ ull pack2(float x, float y) {
    ull r; asm("mov.b64 %0, {%1, %2};" : "=l"(r) : "f"(x), "f"(y)); return r;
}
__device__ __forceinline__ float2 unpack2(ull v) {
    float2 r; asm("mov.b64 {%0, %1}, %2;" : "=f"(r.x), "=f"(r.y) : "l"(v)); return r;
}

// ---------------- neighbor list build (detection inlined) ---------------------
__global__ void __launch_bounds__(256) build_nbr_kernel(const void* m) {
    __shared__ int mode_s;
    if (threadIdx.x < 32) {
        // self-loop diagonal is always true; under byte interpretation the
        // first 32 diagonal bytes all read 1 iff masks are byte-typed.
        bool okb = ((const unsigned char*)m)[(size_t)threadIdx.x * NN + threadIdx.x] == 1;
        unsigned bal = __ballot_sync(0xffffffffu, okb);
        if (threadIdx.x == 0) mode_s = (bal == 0xffffffffu) ? 0 : 1;
    }
    __syncthreads();
    const int mode = mode_s;

    const int gw   = (blockIdx.x * blockDim.x + threadIdx.x) >> 5;
    const int lane = threadIdx.x & 31;
    if (gw >= KH * NN) return;
    int* nb = g_nbr + (size_t)gw * MAXNBR;
    int cnt = 0;

    if (mode == 0) {
        const uint4* p = (const uint4*)((const unsigned char*)m + (size_t)gw * NN);
#pragma unroll
        for (int it = 0; it < NN / 512; ++it) {
            uint4 v = p[it * 32 + lane];
            unsigned w[4] = {v.x, v.y, v.z, v.w};
            int base = it * 512 + lane * 16;
#pragma unroll
            for (int q = 0; q < 4; ++q)
#pragma unroll
                for (int bp = 0; bp < 4; ++bp) {
                    bool mv = ((w[q] >> (8 * bp)) & 0xffu) != 0u;
                    unsigned bal = __ballot_sync(0xffffffffu, mv);
                    if (mv) {
                        int pos = cnt + __popc(bal & ((1u << lane) - 1u));
                        if (pos < MAXNBR) nb[pos] = base + q * 4 + bp;
                    }
                    cnt += __popc(bal);
                }
        }
    } else {
        const uint4* p = (const uint4*)((const unsigned*)m + (size_t)gw * NN);
#pragma unroll 4
        for (int it = 0; it < NN / 128; ++it) {
            uint4 v = p[it * 32 + lane];
            unsigned w[4] = {v.x, v.y, v.z, v.w};
            int base = it * 128 + lane * 4;
#pragma unroll
            for (int q = 0; q < 4; ++q) {
                bool mv = (w[q] != 0u);
                unsigned bal = __ballot_sync(0xffffffffu, mv);
                if (mv) {
                    int pos = cnt + __popc(bal & ((1u << lane) - 1u));
                    if (pos < MAXNBR) nb[pos] = base + q;
                }
                cnt += __popc(bal);
            }
        }
    }
    if (lane == 0) g_cnt[gw] = cnt < MAXNBR ? cnt : MAXNBR;
}

// ---------------- Wh = x @ W (bf16 out) + fused f1/f2, FFMA2 inner loop ------
#define GBM 128
#define GBK 32
__global__ void __launch_bounds__(128) wh_gemm_kernel(
        const float* __restrict__ x, const float* __restrict__ W,
        const float* __restrict__ a1v, const float* __restrict__ a2v) {
    const int h = blockIdx.y, row0 = blockIdx.x * GBM;
    const int tid = threadIdx.x;
    const int tx = tid & 7;
    const int ty = tid >> 3;

    __shared__ ull   xsd[GBK][GBM];
    __shared__ float ws [GBK][DH];

    ull acc[8][4];
#pragma unroll
    for (int i = 0; i < 8; ++i)
#pragma unroll
        for (int j = 0; j < 4; ++j) acc[i][j] = 0ULL;

    for (int k0 = 0; k0 < FIN; k0 += GBK) {
#pragma unroll
        for (int pass = 0; pass < 4; ++pass) {
            int r = pass * 32 + (tid >> 2);
            int seg = tid & 3;
            const float4* xp = (const float4*)(x + (size_t)(row0 + r) * FIN + k0 + seg * 8);
            float4 v0 = xp[0], v1 = xp[1];
            xsd[seg * 8 + 0][r] = pack2(v0.x, v0.x);
            xsd[seg * 8 + 1][r] = pack2(v0.y, v0.y);
            xsd[seg * 8 + 2][r] = pack2(v0.z, v0.z);
            xsd[seg * 8 + 3][r] = pack2(v0.w, v0.w);
            xsd[seg * 8 + 4][r] = pack2(v1.x, v1.x);
            xsd[seg * 8 + 5][r] = pack2(v1.y, v1.y);
            xsd[seg * 8 + 6][r] = pack2(v1.z, v1.z);
            xsd[seg * 8 + 7][r] = pack2(v1.w, v1.w);
        }
        {
            int s = tid;
#pragma unroll
            for (int rep = 0; rep < 4; ++rep, s += 128) {
                int kk = s >> 4, c4 = (s & 15) * 4;
                float4 v = *(const float4*)(W + ((size_t)h * FIN + k0 + kk) * DH + c4);
                *(float4*)&ws[kk][c4] = v;
            }
        }
        __syncthreads();
#pragma unroll
        for (int kk = 0; kk < GBK; ++kk) {
            ull a[8];
            *(ulonglong2*)&a[0] = *(const ulonglong2*)&xsd[kk][ty * 8 + 0];
            *(ulonglong2*)&a[2] = *(const ulonglong2*)&xsd[kk][ty * 8 + 2];
            *(ulonglong2*)&a[4] = *(const ulonglong2*)&xsd[kk][ty * 8 + 4];
            *(ulonglong2*)&a[6] = *(const ulonglong2*)&xsd[kk][ty * 8 + 6];
            ull b[4];
            *(ulonglong2*)&b[0] = *(const ulonglong2*)&ws[kk][tx * 8 + 0];
            *(ulonglong2*)&b[2] = *(const ulonglong2*)&ws[kk][tx * 8 + 4];
#pragma unroll
            for (int i = 0; i < 8; ++i)
#pragma unroll
                for (int j = 0; j < 4; ++j)
                    fma2(acc[i][j], a[i], b[j]);
        }
        __syncthreads();
    }

    const float* A1 = a1v + h * DH + tx * 8;
    const float* A2 = a2v + h * DH + tx * 8;
    float a1r[8], a2r[8];
#pragma unroll
    for (int c = 0; c < 8; ++c) { a1r[c] = A1[c]; a2r[c] = A2[c]; }

    float* f1s = (float*)xsd;
    float* f2s = f1s + 1024;

#pragma unroll
    for (int i = 0; i < 8; ++i) {
        float v[8];
#pragma unroll
        for (int j = 0; j < 4; ++j) {
            float2 u = unpack2(acc[i][j]);
            v[2 * j] = u.x; v[2 * j + 1] = u.y;
        }
        int row = row0 + ty * 8 + i;
        __nv_bfloat162* dst = g_Whb + ((size_t)h * NN + row) * 32 + tx * 4;
        dst[0] = __floats2bfloat162_rn(v[0], v[1]);
        dst[1] = __floats2bfloat162_rn(v[2], v[3]);
        dst[2] = __floats2bfloat162_rn(v[4], v[5]);
        dst[3] = __floats2bfloat162_rn(v[6], v[7]);
        float p1 = 0.f, p2 = 0.f;
#pragma unroll
        for (int c = 0; c < 8; ++c) { p1 += v[c] * a1r[c]; p2 += v[c] * a2r[c]; }
        f1s[tx * 128 + ty * 8 + i] = p1;
        f2s[tx * 128 + ty * 8 + i] = p2;
    }
    __syncthreads();
    {
        int r = tid;
        float s1 = 0.f, s2 = 0.f;
#pragma unroll
        for (int g = 0; g < 8; ++g) { s1 += f1s[g * 128 + r]; s2 += f2s[g * 128 + r]; }
        g_f1[h * NN + row0 + r] = s1;
        g_f2[h * NN + row0 + r] = s2;
    }
}

// ---------------- layer-1: block per node, warp per head, fused Who/g1/g2 ----
__global__ void __launch_bounds__(256) gat1_kernel(
        const float* __restrict__ Wout,
        const float* __restrict__ ao1, const float* __restrict__ ao2) {
    const int n    = blockIdx.x;
    const int tid  = threadIdx.x;
    const int h    = tid >> 5;
    const int lane = tid & 31;
    const int q    = lane & 15;
    const int half = lane >> 4;

    __shared__ int   nbs[KH][MAXNBR];   // 4 KB
    __shared__ ull   pd[NH][MAXNBR];    // 32 KB (weight, byte-offset) per head
    __shared__ float xrow[NH * DH];     // 2 KB
    __shared__ float who_s[NC];

    const int c0 = g_cnt[n];
    const int c1 = g_cnt[NN + n];
    for (int j = tid; j < c0; j += 256) nbs[0][j] = g_nbr[(size_t)n * MAXNBR + j];
    for (int j = tid; j < c1; j += 256) nbs[1][j] = g_nbr[(size_t)(NN + n) * MAXNBR + j];
    __syncthreads();

    const float  f1v = g_f1[h * NN + n];
    const float* f2h = g_f2 + h * NN;
    const char*  whq = (const char*)(g_Whb + (size_t)h * NN * 32) + q * 8;

    float t0 = 0.f, t1 = 0.f, t2 = 0.f, t3 = 0.f;
    const int cs[2] = {c0, c1};

#pragma unroll
    for (int hop = 0; hop < KH; ++hop) {
        const int cnt = cs[hop];

        float lsum = 0.f;
        for (int j = lane; j < cnt; j += 32) {
            int nbj = nbs[hop][j];
            float v = f1v + __ldg(f2h + nbj);
            v = v > 0.f ? v : 0.2f * v;
            float ex = __expf(v);               // e bounded: skip max pass
            pd[h][j] = ((ull)(unsigned)(nbj << 7) << 32) | (ull)__float_as_uint(ex);
            lsum += ex;
        }
#pragma unroll
        for (int s = 16; s > 0; s >>= 1)
            lsum += __shfl_xor_sync(0xffffffffu, lsum, s);
        __syncwarp();
        const float scale = (hop ? 0.9f : 1.0f) / lsum;

        float a0 = 0.f, a1 = 0.f, a2 = 0.f, a3 = 0.f;
        for (int j = half; j < cnt; j += 2) {
            ull pv = pd[h][j];
            float    p   = __uint_as_float((unsigned)pv);
            unsigned off = (unsigned)(pv >> 32);
            ull w2 = *(const ull*)(whq + off);
            unsigned wlo = (unsigned)w2, whi = (unsigned)(w2 >> 32);
            float f0 = __uint_as_float(wlo << 16);
            float f1_ = __uint_as_float(wlo & 0xffff0000u);
            float f2_ = __uint_as_float(whi << 16);
            float f3 = __uint_as_float(whi & 0xffff0000u);
            a0 += p * f0; a1 += p * f1_; a2 += p * f2_; a3 += p * f3;
        }
        t0 += scale * a0; t1 += scale * a1; t2 += scale * a2; t3 += scale * a3;
        __syncwarp();
    }

    // combine the two half-warp neighbor partitions
    t0 += __shfl_xor_sync(0xffffffffu, t0, 16);
    t1 += __shfl_xor_sync(0xffffffffu, t1, 16);
    t2 += __shfl_xor_sync(0xffffffffu, t2, 16);
    t3 += __shfl_xor_sync(0xffffffffu, t3, 16);

    if (half == 0) {
        t0 = t0 > 0.f ? t0 : (__expf(t0) - 1.f);
        t1 = t1 > 0.f ? t1 : (__expf(t1) - 1.f);
        t2 = t2 > 0.f ? t2 : (__expf(t2) - 1.f);
        t3 = t3 > 0.f ? t3 : (__expf(t3) - 1.f);
        *(float4*)&xrow[h * DH + q * 4] = make_float4(t0, t1, t2, t3);
    }
    __syncthreads();

    // fused Who row: warp h computes classes 2h and 2h+1 (W_out L1-resident)
#pragma unroll
    for (int ci = 0; ci < 2; ++ci) {
        const int cc = 2 * h + ci;
        float s = 0.f;
#pragma unroll
        for (int k0 = 0; k0 < FIN; k0 += 32)
            s += xrow[k0 + lane] * __ldg(Wout + (size_t)(k0 + lane) * NC + cc);
#pragma unroll
        for (int sft = 16; sft > 0; sft >>= 1)
            s += __shfl_xor_sync(0xffffffffu, s, sft);
        if (lane == 0) {
            who_s[cc] = s;
            g_Who[(size_t)n * NC + cc] = s;
        }
    }
    __syncthreads();
    if (tid == 0) {
        float gg = 0.f;
#pragma unroll
        for (int cc = 0; cc < NC; ++cc) gg += who_s[cc] * ao1[cc];
        g_g1[n] = gg;
    }
    if (tid == 1) {
        float gg = 0.f;
#pragma unroll
        for (int cc = 0; cc < NC; ++cc) gg += who_s[cc] * ao2[cc];
        g_g2[n] = gg;
    }
}

// ---------------- output sparse attention + elu + log_softmax -----------------
__global__ void __launch_bounds__(128) out_kernel(float* __restrict__ out) {
    const int wi   = threadIdx.x >> 5;
    const int n    = blockIdx.x * 4 + wi;
    const int lane = threadIdx.x & 31;
    const int c    = lane & 15;
    const int half = lane >> 4;

    __shared__ ull pd[4][MAXNBR];   // (weight, byte-offset)

    const float g1v = g_g1[n];
    float acc = 0.f;

#pragma unroll
    for (int hop = 0; hop < KH; ++hop) {
        const int  w   = hop * NN + n;
        const int  cnt = g_cnt[w];
        const int* nbg = g_nbr + (size_t)w * MAXNBR;

        float lsum = 0.f;
        for (int j = lane; j < cnt; j += 32) {
            int nbj = nbg[j];
            float v = g1v + g_g2[nbj];
            v = v > 0.f ? v : 0.2f * v;
            float ex = __expf(v);
            pd[wi][j] = ((ull)(unsigned)(nbj << 6) << 32) | (ull)__float_as_uint(ex);
            lsum += ex;
        }
#pragma unroll
        for (int s = 16; s > 0; s >>= 1)
            lsum += __shfl_xor_sync(0xffffffffu, lsum, s);
        __syncwarp();

        const char* whoc = (const char*)g_Who + c * 4;
        float part = 0.f;
        for (int j = half; j < cnt; j += 2) {
            ull pv = pd[wi][j];
            float    p   = __uint_as_float((unsigned)pv);
            unsigned off = (unsigned)(pv >> 32);
            part += p * *(const float*)(whoc + off);
        }
        acc += ((hop ? 0.9f : 1.0f) / lsum) * part;
        __syncwarp();
    }
    acc += __shfl_xor_sync(0xffffffffu, acc, 16);

    float v = acc > 0.f ? acc : (__expf(acc) - 1.f);
    float mx = v;
#pragma unroll
    for (int s = 8; s > 0; s >>= 1)
        mx = fmaxf(mx, __shfl_xor_sync(0xffffffffu, mx, s));
    float ex = __expf(v - mx);
    float sum = ex;
#pragma unroll
    for (int s = 8; s > 0; s >>= 1)
        sum += __shfl_xor_sync(0xffffffffu, sum, s);
    if (lane < NC)
        out[(size_t)n * NC + lane] = v - mx - __logf(sum);
}

// ---------------- launch --------------------------------------------------------
extern "C" void kernel_launch(void* const* d_in, const int* in_sizes, int n_in,
                              void* d_out, int out_size) {
    const float* x      = (const float*)d_in[0];
    const void*  masks  = (const void*) d_in[1];
    const float* W      = (const float*)d_in[2];
    const float* a1     = (const float*)d_in[3];
    const float* a2     = (const float*)d_in[4];
    const float* W_out  = (const float*)d_in[5];
    const float* ao1    = (const float*)d_in[6];
    const float* ao2    = (const float*)d_in[7];
    float* out = (float*)d_out;

    build_nbr_kernel<<<(KH * NN * 32) / 256, 256>>>(masks);
    wh_gemm_kernel<<<dim3(NN / GBM, NH), 128>>>(x, W, a1, a2);
    gat1_kernel<<<NN, 256>>>(W_out, ao1, ao2);
    out_kernel<<<NN / 4, 128>>>(out);
}